// round 13
// baseline (speedup 1.0000x reference)
#include <cuda_runtime.h>
#include <cuda_fp16.h>
#include <cstdint>

#define L_DIM   1024
#define OUT_DIM 512
#define M_TOT   16384       // B*N = 64*256
#define BM      128
#define BN      256
#define KC      64
#define NCHUNK  (L_DIM / KC)   // 16
#define NSTAGE  4
#define THREADS 256

// ---------------- device scratch (no allocations allowed) ----------------
__device__ __align__(128) unsigned short g_w[L_DIM * OUT_DIM];    // fp16, [K,N]
__device__ __align__(128) unsigned short g_xh[M_TOT * L_DIM];     // fp16, [M,K] (32MB)
__device__ float g_bc[OUT_DIM];

// ---------------- smem layout (dynamic) ----------------
// bias [0,1024)
// stage: A (x fp16): row stride 144B (64 fp16 = 128B + 16 pad), 128*144 = 18432B
//        B (w fp16): row stride 528B (512B + 16 pad), 64*528 = 33792B
#define SM_STG    1024
#define A_RSTRIDE 144
#define A_TILE    (BM * A_RSTRIDE)             // 18432
#define B_RSTRIDE 528
#define B_TILE    (KC * B_RSTRIDE)             // 33792
#define STG_B_OFF A_TILE
#define STAGE_SZ  (A_TILE + B_TILE)            // 52224
#define SMEM_NEED (SM_STG + NSTAGE * STAGE_SZ) // 209920 bytes (occ 1)

__device__ __forceinline__ uint32_t smem_to_u32(const void* p) {
    uint32_t a;
    asm("{ .reg .u64 t; cvta.to.shared.u64 t, %1; cvt.u32.u64 %0, t; }" : "=r"(a) : "l"(p));
    return a;
}

#define CP_ASYNC16(dst, src) \
    asm volatile("cp.async.cg.shared.global [%0], [%1], 16;" :: "r"(dst), "l"(src) : "memory")
#define CP_COMMIT()   asm volatile("cp.async.commit_group;" ::: "memory")
#define CP_WAIT2()    asm volatile("cp.async.wait_group 2;" ::: "memory")
#define CP_WAIT_ALL() asm volatile("cp.async.wait_group 0;" ::: "memory")

#define LDMATRIX_X4(r0, r1, r2, r3, addr) \
    asm volatile("ldmatrix.sync.aligned.m8n8.x4.shared.b16 {%0,%1,%2,%3}, [%4];" \
        : "=r"(r0), "=r"(r1), "=r"(r2), "=r"(r3) : "r"(addr))
#define LDMATRIX_X4_T(r0, r1, r2, r3, addr) \
    asm volatile("ldmatrix.sync.aligned.m8n8.x4.trans.shared.b16 {%0,%1,%2,%3}, [%4];" \
        : "=r"(r0), "=r"(r1), "=r"(r2), "=r"(r3) : "r"(addr))

#define MMA_FP16(d, a, b) \
    asm volatile("mma.sync.aligned.m16n8k16.row.col.f32.f16.f16.f32 " \
        "{%0,%1,%2,%3}, {%4,%5,%6,%7}, {%8,%9}, {%0,%1,%2,%3};" \
        : "+f"((d)[0]), "+f"((d)[1]), "+f"((d)[2]), "+f"((d)[3]) \
        : "r"((a)[0]), "r"((a)[1]), "r"((a)[2]), "r"((a)[3]), "r"((b)[0]), "r"((b)[1]))

// ---------------- fused prep: x -> fp16, fold weights -> fp16, bias -------
__global__ void prep_all(const float* __restrict__ x,
                         const float* __restrict__ W_in, const float* __restrict__ b_in,
                         const float* __restrict__ W_out, const float* __restrict__ b_out,
                         const float* __restrict__ W_root, const float* __restrict__ b_root) {
    size_t i = ((size_t)blockIdx.x * 256 + threadIdx.x) * 8;
    float4 v0 = *(const float4*)(x + i);
    float4 v1 = *(const float4*)(x + i + 4);
    __half2 h0 = __floats2half2_rn(v0.x, v0.y);
    __half2 h1 = __floats2half2_rn(v0.z, v0.w);
    __half2 h2 = __floats2half2_rn(v1.x, v1.y);
    __half2 h3 = __floats2half2_rn(v1.z, v1.w);
    uint4 o;
    o.x = *reinterpret_cast<uint32_t*>(&h0);
    o.y = *reinterpret_cast<uint32_t*>(&h1);
    o.z = *reinterpret_cast<uint32_t*>(&h2);
    o.w = *reinterpret_cast<uint32_t*>(&h3);
    *reinterpret_cast<uint4*>(g_xh + i) = o;

    int wi = blockIdx.x * 256 + threadIdx.x;
    if (wi < L_DIM * OUT_DIM) {
        float wc = 0.5f * W_out[wi] + 0.5f * W_in[wi] + W_root[wi];
        g_w[wi] = __half_as_ushort(__float2half_rn(wc));
    }
    if (wi < OUT_DIM) {
        g_bc[wi] = 0.5f * b_out[wi] + 0.5f * b_in[wi] + b_root[wi];
    }
}

// ---------------- GEMM: 128x256 CTA, warp 64x64, KC=64, 4-stage -----------
__global__ __launch_bounds__(THREADS, 1)
void gemm_hmma(float* __restrict__ y) {
    extern __shared__ char smem[];
    const uint32_t sb = smem_to_u32(smem);
    float* sbias = (float*)smem;

    const int tid  = threadIdx.x;
    const int wid  = tid >> 5;
    const int lane = tid & 31;
    const int m0 = blockIdx.y * BM;
    const int n0 = blockIdx.x * BN;
    const int m_warp = (wid >> 2) * 64;     // 0,64
    const int n_warp = (wid & 3) * 64;      // 0,64,128,192

    sbias[tid] = g_bc[n0 + tid];

    float acc[4][8][4];
#pragma unroll
    for (int i = 0; i < 4; i++)
#pragma unroll
        for (int j = 0; j < 8; j++)
#pragma unroll
            for (int q = 0; q < 4; q++) acc[i][j][q] = 0.0f;

    const char* wp = (const char*)g_w;
    const char* xp = (const char*)g_xh;

    // load one chunk's A+B tiles via cp.async into a stage
    auto cp_tiles = [&](int chunk, int stage) {
        const uint32_t stg = sb + SM_STG + stage * STAGE_SZ;
        const size_t kbase = (size_t)chunk * KC;
        // A: 128 rows x 8 chunks of 16B = 1024 -> 4/thread
#pragma unroll
        for (int j = 0; j < 4; j++) {
            int idx = tid + j * 256;
            int r   = idx >> 3;
            int cb  = (idx & 7) * 16;
            size_t srcoff = ((size_t)(m0 + r) * L_DIM + kbase) * 2 + cb;
            CP_ASYNC16(stg + (uint32_t)(r * A_RSTRIDE + cb), xp + srcoff);
        }
        // B: 64 k-rows x 32 chunks of 16B = 2048 -> 8/thread
#pragma unroll
        for (int j = 0; j < 8; j++) {
            int idx = tid + j * 256;
            int r   = idx >> 5;
            int cb  = (idx & 31) * 16;
            size_t srcoff = ((kbase + r) * OUT_DIM + n0) * 2 + cb;
            CP_ASYNC16(stg + STG_B_OFF + (uint32_t)(r * B_RSTRIDE + cb), wp + srcoff);
        }
    };

    // per-lane frag address components
    uint32_t a_ld_off[4];   // per mi; + ks*32 bytes
#pragma unroll
    for (int mi = 0; mi < 4; mi++)
        a_ld_off[mi] = (uint32_t)((m_warp + mi * 16 + (lane & 15)) * A_RSTRIDE + ((lane >> 4) << 4));
    uint32_t b_ld_off[4];   // per p; + ks*16*B_RSTRIDE bytes
#pragma unroll
    for (int p = 0; p < 4; p++)
        b_ld_off[p] = (uint32_t)((lane & 15) * B_RSTRIDE + (n_warp + p * 16 + ((lane >> 4) << 3)) * 2);

    auto load_frags = [&](uint32_t astg, uint32_t bstg, int ks, uint32_t af[4][4], uint32_t bf[8][2]) {
#pragma unroll
        for (int p = 0; p < 4; p++) {
            uint32_t addr = bstg + (uint32_t)(ks * 16 * B_RSTRIDE) + b_ld_off[p];
            LDMATRIX_X4_T(bf[p * 2][0], bf[p * 2][1], bf[p * 2 + 1][0], bf[p * 2 + 1][1], addr);
        }
#pragma unroll
        for (int mi = 0; mi < 4; mi++) {
            uint32_t ra = astg + a_ld_off[mi] + ks * 32;
            LDMATRIX_X4(af[mi][0], af[mi][1], af[mi][2], af[mi][3], ra);
        }
    };

    // ---- prologue: issue stages 0,1,2 ----
    cp_tiles(0, 0); CP_COMMIT();
    cp_tiles(1, 1); CP_COMMIT();
    cp_tiles(2, 2); CP_COMMIT();

    uint32_t af[2][4][4], bf[2][8][2];

    // ---- main loop (16 chunks x 4 ks) ----
    for (int i = 0; i < NCHUNK; i++) {
        const int s = i & (NSTAGE - 1);

        // group i must have landed (groups i+1, i+2 may remain in flight)
        CP_WAIT2();
        __syncthreads();

        // refill: issue chunk i+3 into the stage consumed at chunk i-1
        if (i + 3 < NCHUNK) {
            cp_tiles(i + 3, (i + 3) & (NSTAGE - 1));
            CP_COMMIT();
        } else {
            // keep group accounting uniform for CP_WAIT2
            CP_COMMIT();
        }

        const uint32_t astg = sb + SM_STG + s * STAGE_SZ;
        const uint32_t bstg = astg + STG_B_OFF;

        load_frags(astg, bstg, 0, af[0], bf[0]);
#pragma unroll
        for (int ks = 0; ks < 4; ks++) {
            const int cur = ks & 1;
            const int nxt = cur ^ 1;
            if (ks + 1 < 4) load_frags(astg, bstg, ks + 1, af[nxt], bf[nxt]);
#pragma unroll
            for (int mi = 0; mi < 4; mi++)
#pragma unroll
                for (int nj = 0; nj < 8; nj++)
                    MMA_FP16(acc[mi][nj], af[cur][mi], bf[cur][nj]);
        }
    }

    // ---- epilogue: bias add + store ----
#pragma unroll
    for (int mi = 0; mi < 4; mi++) {
        int r0 = m0 + m_warp + mi * 16 + (lane >> 2);
#pragma unroll
        for (int nj = 0; nj < 8; nj++) {
            int cl = n_warp + nj * 8 + (lane & 3) * 2;
            float b0 = sbias[cl], b1 = sbias[cl + 1];
            float2 v0 = make_float2(acc[mi][nj][0] + b0, acc[mi][nj][1] + b1);
            float2 v1 = make_float2(acc[mi][nj][2] + b0, acc[mi][nj][3] + b1);
            *(float2*)(y + (size_t)r0 * OUT_DIM + n0 + cl) = v0;
            *(float2*)(y + (size_t)(r0 + 8) * OUT_DIM + n0 + cl) = v1;
        }
    }
}

// ---------------- launch ----------------
extern "C" void kernel_launch(void* const* d_in, const int* in_sizes, int n_in,
                              void* d_out, int out_size) {
    // metadata order: x, At, W_in, b_in, W_out, b_out, W_root, b_root
    const float* x      = (const float*)d_in[0];
    // d_in[1] = At — mathematically dead (ChebConv K=1: no neighbor aggregation)
    const float* W_in   = (const float*)d_in[2];
    const float* b_in   = (const float*)d_in[3];
    const float* W_out  = (const float*)d_in[4];
    const float* b_out  = (const float*)d_in[5];
    const float* W_root = (const float*)d_in[6];
    const float* b_root = (const float*)d_in[7];
    float* y = (float*)d_out;

    prep_all<<<M_TOT * L_DIM / (256 * 8), 256>>>(x, W_in, b_in, W_out, b_out, W_root, b_root);

    cudaFuncSetAttribute(gemm_hmma, cudaFuncAttributeMaxDynamicSharedMemorySize, SMEM_NEED);
    gemm_hmma<<<dim3(OUT_DIM / BN, M_TOT / BM), THREADS, SMEM_NEED>>>(y);
}

// round 14
// speedup vs baseline: 1.1799x; 1.1799x over previous
#include <cuda_runtime.h>
#include <cuda_fp16.h>
#include <cstdint>

#define L_DIM   1024
#define OUT_DIM 512
#define M_TOT   16384       // B*N = 64*256
#define BM      128
#define BN      256
#define KC      64
#define NCHUNK  (L_DIM / KC)   // 16
#define THREADS 256

// ---------------- device scratch (no allocations allowed) ----------------
__device__ __align__(128) unsigned short g_w[L_DIM * OUT_DIM];  // fp16, [K,N]
__device__ float g_bc[OUT_DIM];

// ---------------- smem layout (dynamic) ----------------
// bias [0,1024)
// stage: A (x fp16): row stride 144B (64 fp16 = 128B + 16 pad), 128*144 = 18432B
//        B (w fp16): row stride 528B (512B + 16 pad), 64*528 = 33792B
#define SM_STG    1024
#define A_RSTRIDE 144
#define A_TILE    (BM * A_RSTRIDE)             // 18432
#define B_RSTRIDE 528
#define B_TILE    (KC * B_RSTRIDE)             // 33792
#define STG_B_OFF A_TILE
#define STAGE_SZ  (A_TILE + B_TILE)            // 52224
#define SMEM_NEED (SM_STG + 2 * STAGE_SZ)      // 105472

__device__ __forceinline__ uint32_t smem_to_u32(const void* p) {
    uint32_t a;
    asm("{ .reg .u64 t; cvta.to.shared.u64 t, %1; cvt.u32.u64 %0, t; }" : "=r"(a) : "l"(p));
    return a;
}

#define CP_ASYNC16(dst, src) \
    asm volatile("cp.async.cg.shared.global [%0], [%1], 16;" :: "r"(dst), "l"(src) : "memory")
#define CP_COMMIT()   asm volatile("cp.async.commit_group;" ::: "memory")
#define CP_WAIT_ALL() asm volatile("cp.async.wait_group 0;" ::: "memory")

#define LDMATRIX_X4(r0, r1, r2, r3, addr) \
    asm volatile("ldmatrix.sync.aligned.m8n8.x4.shared.b16 {%0,%1,%2,%3}, [%4];" \
        : "=r"(r0), "=r"(r1), "=r"(r2), "=r"(r3) : "r"(addr))
#define LDMATRIX_X4_T(r0, r1, r2, r3, addr) \
    asm volatile("ldmatrix.sync.aligned.m8n8.x4.trans.shared.b16 {%0,%1,%2,%3}, [%4];" \
        : "=r"(r0), "=r"(r1), "=r"(r2), "=r"(r3) : "r"(addr))

#define MMA_FP16(d, a, b) \
    asm volatile("mma.sync.aligned.m16n8k16.row.col.f32.f16.f16.f32 " \
        "{%0,%1,%2,%3}, {%4,%5,%6,%7}, {%8,%9}, {%0,%1,%2,%3};" \
        : "+f"((d)[0]), "+f"((d)[1]), "+f"((d)[2]), "+f"((d)[3]) \
        : "r"((a)[0]), "r"((a)[1]), "r"((a)[2]), "r"((a)[3]), "r"((b)[0]), "r"((b)[1]))

// ---------------- prep: fold 3 linears -> fp16 (weights only) -------------
__global__ void prep_weights(const float* __restrict__ W_in, const float* __restrict__ b_in,
                             const float* __restrict__ W_out, const float* __restrict__ b_out,
                             const float* __restrict__ W_root, const float* __restrict__ b_root) {
    int i = blockIdx.x * blockDim.x + threadIdx.x;
    if (i < L_DIM * OUT_DIM) {
        float wc = 0.5f * W_out[i] + 0.5f * W_in[i] + W_root[i];
        g_w[i] = __half_as_ushort(__float2half_rn(wc));
    }
    if (i < OUT_DIM) {
        g_bc[i] = 0.5f * b_out[i] + 0.5f * b_in[i] + b_root[i];
    }
}

// ---------------- GEMM: 128x256 CTA, warp 64x64, KC=64, in-loop x cvt -----
__global__ __launch_bounds__(THREADS, 1)
void gemm_hmma(const float* __restrict__ x, float* __restrict__ y) {
    extern __shared__ char smem[];
    const uint32_t sb = smem_to_u32(smem);
    float* sbias = (float*)smem;

    const int tid  = threadIdx.x;
    const int wid  = tid >> 5;
    const int lane = tid & 31;
    const int m0 = blockIdx.y * BM;
    const int n0 = blockIdx.x * BN;
    const int m_warp = (wid >> 2) * 64;     // 0,64
    const int n_warp = (wid & 3) * 64;      // 0,64,128,192

    sbias[tid] = g_bc[n0 + tid];

    float acc[4][8][4];
#pragma unroll
    for (int i = 0; i < 4; i++)
#pragma unroll
        for (int j = 0; j < 8; j++)
#pragma unroll
            for (int q = 0; q < 4; q++) acc[i][j][q] = 0.0f;

    const char* wp = (const char*)g_w;

    auto cp_b_tile = [&](int chunk, int stage) {
        const uint32_t bdst = sb + SM_STG + stage * STAGE_SZ + STG_B_OFF;
        const size_t kbase = (size_t)chunk * KC;
#pragma unroll
        for (int j = 0; j < 8; j++) {
            int idx = tid + j * 256;             // 0..2047 = 64 rows x 32 chunks of 16B
            int r   = idx >> 5;
            int cb  = (idx & 31) * 16;
            size_t srcoff = ((kbase + r) * OUT_DIM + n0) * 2 + cb;
            CP_ASYNC16(bdst + (uint32_t)(r * B_RSTRIDE + cb), wp + srcoff);
        }
    };

    // A: LDG fp32 (L2-resident), cvt to fp16 in regs, STS (hi only)
    auto ldg_a = [&](int chunk, float4* av) {
        const float* src = x + (size_t)m0 * L_DIM + (size_t)chunk * KC;
#pragma unroll
        for (int j = 0; j < 8; j++) {
            int idx = tid + j * 256;             // 0..2047 = 128 rows x 16 float4
            int r   = idx >> 4;
            int cb  = idx & 15;
            av[j] = *(const float4*)(src + (size_t)r * L_DIM + cb * 4);
        }
    };

    auto sts_a = [&](const float4* av, int stage) {
        const uint32_t ah = sb + SM_STG + stage * STAGE_SZ;
#pragma unroll
        for (int j = 0; j < 8; j++) {
            int idx = tid + j * 256;
            int r   = idx >> 4;
            int cb  = idx & 15;
            __half2 h0 = __floats2half2_rn(av[j].x, av[j].y);
            __half2 h1 = __floats2half2_rn(av[j].z, av[j].w);
            uint32_t u0 = *reinterpret_cast<uint32_t*>(&h0);
            uint32_t u1 = *reinterpret_cast<uint32_t*>(&h1);
            uint32_t off = (uint32_t)(r * A_RSTRIDE + cb * 8);
            asm volatile("st.shared.v2.b32 [%0], {%1,%2};" :: "r"(ah + off), "r"(u0), "r"(u1) : "memory");
        }
    };

    // per-lane frag address components
    uint32_t a_ld_off[4];   // per mi; + ks*32 bytes
#pragma unroll
    for (int mi = 0; mi < 4; mi++)
        a_ld_off[mi] = (uint32_t)((m_warp + mi * 16 + (lane & 15)) * A_RSTRIDE + ((lane >> 4) << 4));
    uint32_t b_ld_off[4];   // per p; + ks*16*B_RSTRIDE bytes
#pragma unroll
    for (int p = 0; p < 4; p++)
        b_ld_off[p] = (uint32_t)((lane & 15) * B_RSTRIDE + (n_warp + p * 16 + ((lane >> 4) << 3)) * 2);

    // ---- prologue: fill stage 0 ----
    cp_b_tile(0, 0);
    CP_COMMIT();
    float4 av[8];
    ldg_a(0, av);
    sts_a(av, 0);
    CP_WAIT_ALL();
    __syncthreads();

    // ---- main loop (16 chunks x 4 ks) ----
    for (int i = 0; i < NCHUNK; i++) {
        const int s = i & 1;
        const int o = s ^ 1;
        const bool have_next = (i + 1 < NCHUNK);

        if (have_next) {
            ldg_a(i + 1, av);
            cp_b_tile(i + 1, o);
            CP_COMMIT();
        }

        const uint32_t astg = sb + SM_STG + s * STAGE_SZ;
        const uint32_t bstg = astg + STG_B_OFF;

#pragma unroll
        for (int ks = 0; ks < 4; ks++) {
            uint32_t bf[8][2], af[4][4];
#pragma unroll
            for (int p = 0; p < 4; p++) {
                uint32_t addr = bstg + (uint32_t)(ks * 16 * B_RSTRIDE) + b_ld_off[p];
                LDMATRIX_X4_T(bf[p * 2][0], bf[p * 2][1], bf[p * 2 + 1][0], bf[p * 2 + 1][1], addr);
            }
#pragma unroll
            for (int mi = 0; mi < 4; mi++) {
                uint32_t ra = astg + a_ld_off[mi] + ks * 32;
                LDMATRIX_X4(af[mi][0], af[mi][1], af[mi][2], af[mi][3], ra);
            }
#pragma unroll
            for (int mi = 0; mi < 4; mi++)
#pragma unroll
                for (int nj = 0; nj < 8; nj++)
                    MMA_FP16(acc[mi][nj], af[mi], bf[nj]);
        }

        if (have_next) sts_a(av, o);

        CP_WAIT_ALL();
        __syncthreads();
    }

    // ---- epilogue: bias add + store ----
#pragma unroll
    for (int mi = 0; mi < 4; mi++) {
        int r0 = m0 + m_warp + mi * 16 + (lane >> 2);
#pragma unroll
        for (int nj = 0; nj < 8; nj++) {
            int cl = n_warp + nj * 8 + (lane & 3) * 2;
            float b0 = sbias[cl], b1 = sbias[cl + 1];
            float2 v0 = make_float2(acc[mi][nj][0] + b0, acc[mi][nj][1] + b1);
            float2 v1 = make_float2(acc[mi][nj][2] + b0, acc[mi][nj][3] + b1);
            *(float2*)(y + (size_t)r0 * OUT_DIM + n0 + cl) = v0;
            *(float2*)(y + (size_t)(r0 + 8) * OUT_DIM + n0 + cl) = v1;
        }
    }
}

// ---------------- launch ----------------
extern "C" void kernel_launch(void* const* d_in, const int* in_sizes, int n_in,
                              void* d_out, int out_size) {
    // metadata order: x, At, W_in, b_in, W_out, b_out, W_root, b_root
    const float* x      = (const float*)d_in[0];
    // d_in[1] = At — mathematically dead (ChebConv K=1: no neighbor aggregation)
    const float* W_in   = (const float*)d_in[2];
    const float* b_in   = (const float*)d_in[3];
    const float* W_out  = (const float*)d_in[4];
    const float* b_out  = (const float*)d_in[5];
    const float* W_root = (const float*)d_in[6];
    const float* b_root = (const float*)d_in[7];
    float* y = (float*)d_out;

    prep_weights<<<(L_DIM * OUT_DIM + 255) / 256, 256>>>(W_in, b_in, W_out, b_out, W_root, b_root);

    cudaFuncSetAttribute(gemm_hmma, cudaFuncAttributeMaxDynamicSharedMemorySize, SMEM_NEED);
    gemm_hmma<<<dim3(OUT_DIM / BN, M_TOT / BM), THREADS, SMEM_NEED>>>(x, y);
}

// round 15
// speedup vs baseline: 1.1849x; 1.0042x over previous
#include <cuda_runtime.h>
#include <cuda_fp16.h>
#include <cstdint>

#define L_DIM   1024
#define OUT_DIM 512
#define M_TOT   16384       // B*N = 64*256
#define BM      128
#define BN      256
#define KC      64
#define NCHUNK  (L_DIM / KC)   // 16
#define THREADS 256

// ---------------- device scratch (no allocations allowed) ----------------
__device__ __align__(128) unsigned short g_w[L_DIM * OUT_DIM];  // fp16, [K,N]
__device__ float g_bc[OUT_DIM];

// ---------------- smem layout (dynamic) ----------------
// bias [0,1024)
// stage: A (x fp16): row stride 144B (64 fp16 = 128B + 16 pad), 128*144 = 18432B
//        B (w fp16): row stride 528B (512B + 16 pad), 64*528 = 33792B
#define SM_STG    1024
#define A_RSTRIDE 144
#define A_TILE    (BM * A_RSTRIDE)             // 18432
#define B_RSTRIDE 528
#define B_TILE    (KC * B_RSTRIDE)             // 33792
#define STG_B_OFF A_TILE
#define STAGE_SZ  (A_TILE + B_TILE)            // 52224
#define SMEM_NEED (SM_STG + 2 * STAGE_SZ)      // 105472

__device__ __forceinline__ uint32_t smem_to_u32(const void* p) {
    uint32_t a;
    asm("{ .reg .u64 t; cvta.to.shared.u64 t, %1; cvt.u32.u64 %0, t; }" : "=r"(a) : "l"(p));
    return a;
}

#define CP_ASYNC16(dst, src) \
    asm volatile("cp.async.cg.shared.global [%0], [%1], 16;" :: "r"(dst), "l"(src) : "memory")
#define CP_COMMIT()   asm volatile("cp.async.commit_group;" ::: "memory")
#define CP_WAIT_ALL() asm volatile("cp.async.wait_group 0;" ::: "memory")

#define LDMATRIX_X4(r0, r1, r2, r3, addr) \
    asm volatile("ldmatrix.sync.aligned.m8n8.x4.shared.b16 {%0,%1,%2,%3}, [%4];" \
        : "=r"(r0), "=r"(r1), "=r"(r2), "=r"(r3) : "r"(addr))
#define LDMATRIX_X4_T(r0, r1, r2, r3, addr) \
    asm volatile("ldmatrix.sync.aligned.m8n8.x4.trans.shared.b16 {%0,%1,%2,%3}, [%4];" \
        : "=r"(r0), "=r"(r1), "=r"(r2), "=r"(r3) : "r"(addr))

#define MMA_FP16(d, a, b) \
    asm volatile("mma.sync.aligned.m16n8k16.row.col.f32.f16.f16.f32 " \
        "{%0,%1,%2,%3}, {%4,%5,%6,%7}, {%8,%9}, {%0,%1,%2,%3};" \
        : "+f"((d)[0]), "+f"((d)[1]), "+f"((d)[2]), "+f"((d)[3]) \
        : "r"((a)[0]), "r"((a)[1]), "r"((a)[2]), "r"((a)[3]), "r"((b)[0]), "r"((b)[1]))

// ---------------- prep: fold 3 linears -> fp16 (vectorized float4 x2) -----
__global__ void prep_weights(const float* __restrict__ W_in, const float* __restrict__ b_in,
                             const float* __restrict__ W_out, const float* __restrict__ b_out,
                             const float* __restrict__ W_root, const float* __restrict__ b_root) {
    int base = (blockIdx.x * 256 + threadIdx.x) * 8;   // 256 blocks x 256 thr x 8 = 524288
    const float4* wi = (const float4*)(W_in  + base);
    const float4* wo = (const float4*)(W_out + base);
    const float4* wr = (const float4*)(W_root + base);
    uint4 out;
    uint32_t* op = &out.x;
#pragma unroll
    for (int j = 0; j < 2; j++) {
        float4 a = wi[j], b = wo[j], c = wr[j];
        float f0 = 0.5f * b.x + 0.5f * a.x + c.x;
        float f1 = 0.5f * b.y + 0.5f * a.y + c.y;
        float f2 = 0.5f * b.z + 0.5f * a.z + c.z;
        float f3 = 0.5f * b.w + 0.5f * a.w + c.w;
        __half2 h0 = __floats2half2_rn(f0, f1);
        __half2 h1 = __floats2half2_rn(f2, f3);
        op[j * 2 + 0] = *reinterpret_cast<uint32_t*>(&h0);
        op[j * 2 + 1] = *reinterpret_cast<uint32_t*>(&h1);
    }
    *reinterpret_cast<uint4*>(g_w + base) = out;

    int bi = blockIdx.x * 256 + threadIdx.x;
    if (bi < OUT_DIM) {
        g_bc[bi] = 0.5f * b_out[bi] + 0.5f * b_in[bi] + b_root[bi];
    }
}

// ---------------- GEMM: 128x256 CTA, warp 64x64, KC=64, in-loop x cvt -----
// (unchanged from R14 — proven 63.5us config)
__global__ __launch_bounds__(THREADS, 1)
void gemm_hmma(const float* __restrict__ x, float* __restrict__ y) {
    extern __shared__ char smem[];
    const uint32_t sb = smem_to_u32(smem);
    float* sbias = (float*)smem;

    const int tid  = threadIdx.x;
    const int wid  = tid >> 5;
    const int lane = tid & 31;
    const int m0 = blockIdx.y * BM;
    const int n0 = blockIdx.x * BN;
    const int m_warp = (wid >> 2) * 64;     // 0,64
    const int n_warp = (wid & 3) * 64;      // 0,64,128,192

    sbias[tid] = g_bc[n0 + tid];

    float acc[4][8][4];
#pragma unroll
    for (int i = 0; i < 4; i++)
#pragma unroll
        for (int j = 0; j < 8; j++)
#pragma unroll
            for (int q = 0; q < 4; q++) acc[i][j][q] = 0.0f;

    const char* wp = (const char*)g_w;

    auto cp_b_tile = [&](int chunk, int stage) {
        const uint32_t bdst = sb + SM_STG + stage * STAGE_SZ + STG_B_OFF;
        const size_t kbase = (size_t)chunk * KC;
#pragma unroll
        for (int j = 0; j < 8; j++) {
            int idx = tid + j * 256;             // 0..2047 = 64 rows x 32 chunks of 16B
            int r   = idx >> 5;
            int cb  = (idx & 31) * 16;
            size_t srcoff = ((kbase + r) * OUT_DIM + n0) * 2 + cb;
            CP_ASYNC16(bdst + (uint32_t)(r * B_RSTRIDE + cb), wp + srcoff);
        }
    };

    auto ldg_a = [&](int chunk, float4* av) {
        const float* src = x + (size_t)m0 * L_DIM + (size_t)chunk * KC;
#pragma unroll
        for (int j = 0; j < 8; j++) {
            int idx = tid + j * 256;             // 0..2047 = 128 rows x 16 float4
            int r   = idx >> 4;
            int cb  = idx & 15;
            av[j] = *(const float4*)(src + (size_t)r * L_DIM + cb * 4);
        }
    };

    auto sts_a = [&](const float4* av, int stage) {
        const uint32_t ah = sb + SM_STG + stage * STAGE_SZ;
#pragma unroll
        for (int j = 0; j < 8; j++) {
            int idx = tid + j * 256;
            int r   = idx >> 4;
            int cb  = idx & 15;
            __half2 h0 = __floats2half2_rn(av[j].x, av[j].y);
            __half2 h1 = __floats2half2_rn(av[j].z, av[j].w);
            uint32_t u0 = *reinterpret_cast<uint32_t*>(&h0);
            uint32_t u1 = *reinterpret_cast<uint32_t*>(&h1);
            uint32_t off = (uint32_t)(r * A_RSTRIDE + cb * 8);
            asm volatile("st.shared.v2.b32 [%0], {%1,%2};" :: "r"(ah + off), "r"(u0), "r"(u1) : "memory");
        }
    };

    // per-lane frag address components
    uint32_t a_ld_off[4];   // per mi; + ks*32 bytes
#pragma unroll
    for (int mi = 0; mi < 4; mi++)
        a_ld_off[mi] = (uint32_t)((m_warp + mi * 16 + (lane & 15)) * A_RSTRIDE + ((lane >> 4) << 4));
    uint32_t b_ld_off[4];   // per p; + ks*16*B_RSTRIDE bytes
#pragma unroll
    for (int p = 0; p < 4; p++)
        b_ld_off[p] = (uint32_t)((lane & 15) * B_RSTRIDE + (n_warp + p * 16 + ((lane >> 4) << 3)) * 2);

    // ---- prologue: fill stage 0 ----
    cp_b_tile(0, 0);
    CP_COMMIT();
    float4 av[8];
    ldg_a(0, av);
    sts_a(av, 0);
    CP_WAIT_ALL();
    __syncthreads();

    // ---- main loop (16 chunks x 4 ks) ----
    for (int i = 0; i < NCHUNK; i++) {
        const int s = i & 1;
        const int o = s ^ 1;
        const bool have_next = (i + 1 < NCHUNK);

        if (have_next) {
            ldg_a(i + 1, av);
            cp_b_tile(i + 1, o);
            CP_COMMIT();
        }

        const uint32_t astg = sb + SM_STG + s * STAGE_SZ;
        const uint32_t bstg = astg + STG_B_OFF;

#pragma unroll
        for (int ks = 0; ks < 4; ks++) {
            uint32_t bf[8][2], af[4][4];
#pragma unroll
            for (int p = 0; p < 4; p++) {
                uint32_t addr = bstg + (uint32_t)(ks * 16 * B_RSTRIDE) + b_ld_off[p];
                LDMATRIX_X4_T(bf[p * 2][0], bf[p * 2][1], bf[p * 2 + 1][0], bf[p * 2 + 1][1], addr);
            }
#pragma unroll
            for (int mi = 0; mi < 4; mi++) {
                uint32_t ra = astg + a_ld_off[mi] + ks * 32;
                LDMATRIX_X4(af[mi][0], af[mi][1], af[mi][2], af[mi][3], ra);
            }
#pragma unroll
            for (int mi = 0; mi < 4; mi++)
#pragma unroll
                for (int nj = 0; nj < 8; nj++)
                    MMA_FP16(acc[mi][nj], af[mi], bf[nj]);
        }

        if (have_next) sts_a(av, o);

        CP_WAIT_ALL();
        __syncthreads();
    }

    // ---- epilogue: bias add + store ----
#pragma unroll
    for (int mi = 0; mi < 4; mi++) {
        int r0 = m0 + m_warp + mi * 16 + (lane >> 2);
#pragma unroll
        for (int nj = 0; nj < 8; nj++) {
            int cl = n_warp + nj * 8 + (lane & 3) * 2;
            float b0 = sbias[cl], b1 = sbias[cl + 1];
            float2 v0 = make_float2(acc[mi][nj][0] + b0, acc[mi][nj][1] + b1);
            float2 v1 = make_float2(acc[mi][nj][2] + b0, acc[mi][nj][3] + b1);
            *(float2*)(y + (size_t)r0 * OUT_DIM + n0 + cl) = v0;
            *(float2*)(y + (size_t)(r0 + 8) * OUT_DIM + n0 + cl) = v1;
        }
    }
}

// ---------------- launch ----------------
extern "C" void kernel_launch(void* const* d_in, const int* in_sizes, int n_in,
                              void* d_out, int out_size) {
    // metadata order: x, At, W_in, b_in, W_out, b_out, W_root, b_root
    const float* x      = (const float*)d_in[0];
    // d_in[1] = At — mathematically dead (ChebConv K=1: no neighbor aggregation)
    const float* W_in   = (const float*)d_in[2];
    const float* b_in   = (const float*)d_in[3];
    const float* W_out  = (const float*)d_in[4];
    const float* b_out  = (const float*)d_in[5];
    const float* W_root = (const float*)d_in[6];
    const float* b_root = (const float*)d_in[7];
    float* y = (float*)d_out;

    prep_weights<<<L_DIM * OUT_DIM / (256 * 8), 256>>>(W_in, b_in, W_out, b_out, W_root, b_root);

    cudaFuncSetAttribute(gemm_hmma, cudaFuncAttributeMaxDynamicSharedMemorySize, SMEM_NEED);
    gemm_hmma<<<dim3(OUT_DIM / BN, M_TOT / BM), THREADS, SMEM_NEED>>>(x, y);
}